// round 14
// baseline (speedup 1.0000x reference)
#include <cuda_runtime.h>

#define Nn    4096
#define Bb    4
#define Kk    8
#define BN    (Bb * Nn)         // 16384 points per cloud
#define TPB   256               // 128 points/block, 2 threads per point
#define PPB   128               // points per block
#define HALF  (Nn / 2)          // candidates per thread
#define CB    64
#define CTPB  256
#define EPSF  1e-12f
#define KINIT 0x7F7FF000u       // huge-float key; |0xFFF -> FLT_MAX threshold

// ---- device scratch (SoA, coalesced) ----
__device__ float g_dens[2 * BN];
__device__ float g_cov [2 * 6 * BN];
__device__ float g_nv  [2 * Kk * 3 * BN];
__device__ float g_part[3 * CB];

// Ladder-insert key v into ascending 9-list of u32 keys (branch-free, no-op
// safe when v exceeds kd[8]).
__device__ __forceinline__ void ladder9(unsigned kd[9], unsigned v) {
#pragma unroll
    for (int t = 0; t < 9; t++) {
        unsigned lo = umin(kd[t], v);
        v = umax(kd[t], v);
        kd[t] = lo;
    }
}

// Scan HALF candidates from j0; keep 9 smallest (d2, idx) packed keys.
// key = (bits(max(d2,0)) & ~0xFFF) | j  -> unsigned order == (d2_trunc, j).
__device__ __forceinline__ void scan9(const float4* __restrict__ s, int j0,
                                      float px, float py, float pz, float sq,
                                      unsigned kd[9]) {
#pragma unroll
    for (int t = 0; t < 9; t++) kd[t] = KINIT;
    const float m2x = -2.0f * px, m2y = -2.0f * py, m2z = -2.0f * pz;
    float thrf = __uint_as_float(KINIT | 0xFFFu);   // conservative threshold
    const int jend = j0 + HALF;
#pragma unroll 4
    for (int j = j0; j < jend; j++) {
        float4 q = s[j];
        float base = sq + q.w;
        float d2 = fmaf(m2x, q.x, fmaf(m2y, q.y, fmaf(m2z, q.z, base)));
        if (__any_sync(0xffffffffu, d2 <= thrf)) {
            float vc = fmaxf(d2, 0.0f);
            unsigned v = (__float_as_uint(vc) & 0xFFFFF000u) | (unsigned)j;
            ladder9(kd, v);
            thrf = __uint_as_float(kd[8] | 0xFFFu);
        }
    }
}

// Block: 128 points of one (batch, cloud), 2 threads/point (candidate halves).
// 256 blocks -> 2 CTAs/SM on most SMs (8 warps/SMSP), all 148 SMs busy.
__global__ void __launch_bounds__(TPB)
knn_scan_kernel(const float* __restrict__ pred, const float* __restrict__ target) {
    extern __shared__ char smem_raw[];
    float4*   sc   = (float4*)smem_raw;                           // [Nn] cloud
    unsigned* lstk = (unsigned*)(smem_raw + Nn * sizeof(float4)); // [PPB*9]

    const int tid  = threadIdx.x;
    const int b    = blockIdx.y;
    const int c    = blockIdx.z;             // 0 = pred, 1 = target
    const int pl   = tid & (PPB - 1);        // local point
    const int half = tid >> 7;               // candidate half 0/1

    const float* src = (c == 0 ? pred : target) + (size_t)b * Nn * 3;
    for (int p = tid; p < Nn; p += TPB) {
        float x = src[3*p+0], y = src[3*p+1], z = src[3*p+2];
        sc[p] = make_float4(x, y, z, fmaf(x, x, fmaf(y, y, z*z)));
    }
    __syncthreads();

    const int i  = blockIdx.x * PPB + pl;
    const float4 Pi = sc[i];

    unsigned kd[9];
    scan9(sc, half * HALF, Pi.x, Pi.y, Pi.z, Pi.w, kd);

    // half-B publishes its sorted key list (stride-9 -> conflict-free)
    if (half == 1) {
        unsigned* dd = lstk + pl * 9;
#pragma unroll
        for (int t = 0; t < 9; t++) dd[t] = kd[t];
    }
    __syncthreads();
    if (half == 1) return;

    // merge: ladder-insert B's 9 keys into A's list (keys unique -> exact)
    {
        const unsigned* dd = lstk + pl * 9;
#pragma unroll
        for (int m = 0; m < 9; m++) ladder9(kd, dd[m]);
    }

    // ---- epilogue: slots 1..8 are the 8 neighbors (slot 0 = self) ----
    const int base = b * Nn + i;
    float dens = 0.f;
    float cxx = 0.f, cyy = 0.f, czz = 0.f, cxy = 0.f, cxz = 0.f, cyz = 0.f;
#pragma unroll
    for (int k = 0; k < Kk; k++) {
        int j = (int)(kd[k+1] & 0xFFFu);
        float4 q = sc[j];
        float vx = q.x - Pi.x, vy = q.y - Pi.y, vz = q.z - Pi.z;
        cxx = fmaf(vx, vx, cxx); cyy = fmaf(vy, vy, cyy); czz = fmaf(vz, vz, czz);
        cxy = fmaf(vx, vy, cxy); cxz = fmaf(vx, vz, cxz); cyz = fmaf(vy, vz, cyz);
        float nrm = sqrtf(fmaf(vx, vx, fmaf(vy, vy, vz * vz)));
        dens += fmaxf(nrm, 1e-6f);           // sqrt(max(d2,1e-12))
        float inv = 1.0f / fmaxf(nrm, EPSF);
        g_nv[((c*Kk + k)*3 + 0)*BN + base] = vx * inv;
        g_nv[((c*Kk + k)*3 + 1)*BN + base] = vy * inv;
        g_nv[((c*Kk + k)*3 + 2)*BN + base] = vz * inv;
    }
    g_dens[c*BN + base]        = dens * 0.125f;
    g_cov[(c*6 + 0)*BN + base] = cxx * 0.125f;
    g_cov[(c*6 + 1)*BN + base] = cyy * 0.125f;
    g_cov[(c*6 + 2)*BN + base] = czz * 0.125f;
    g_cov[(c*6 + 3)*BN + base] = cxy * 0.125f;
    g_cov[(c*6 + 4)*BN + base] = cxz * 0.125f;
    g_cov[(c*6 + 5)*BN + base] = cyz * 0.125f;
}

// Pair pred/target stats per point, partial-reduce per block.
__global__ void __launch_bounds__(CTPB)
combine_kernel() {
    const int tid = threadIdx.x;
    const int idx = blockIdx.x * CTPB + tid;

    float dd = g_dens[idx] - g_dens[BN + idx];
    float c_den = dd * dd;

    float fro = 0.f;
#pragma unroll
    for (int s = 0; s < 6; s++) {
        float e = g_cov[s*BN + idx] - g_cov[(6 + s)*BN + idx];
        float w = (s < 3) ? 1.0f : 2.0f;
        fro = fmaf(w * e, e, fro);
    }
    float c_cur = sqrtf(fro);

    float dsum = 0.f;
#pragma unroll
    for (int e = 0; e < Kk * 3; e++)
        dsum = fmaf(g_nv[e*BN + idx], g_nv[(Kk*3 + e)*BN + idx], dsum);

    __shared__ float r[3 * CTPB];
    r[tid]          = c_den;
    r[CTPB + tid]   = dsum;
    r[2*CTPB + tid] = c_cur;
    __syncthreads();
#pragma unroll
    for (int s = CTPB / 2; s > 0; s >>= 1) {
        if (tid < s) {
            r[tid]          += r[tid + s];
            r[CTPB + tid]   += r[CTPB + tid + s];
            r[2*CTPB + tid] += r[2*CTPB + tid + s];
        }
        __syncthreads();
    }
    if (tid == 0) {
        g_part[blockIdx.x]        = r[0];
        g_part[CB + blockIdx.x]   = r[CTPB];
        g_part[2*CB + blockIdx.x] = r[2*CTPB];
    }
}

__global__ void __launch_bounds__(CB) finalize_kernel(float* __restrict__ out) {
    __shared__ float r[3 * CB];
    int tid = threadIdx.x;
    r[tid]        = g_part[tid];
    r[CB + tid]   = g_part[CB + tid];
    r[2*CB + tid] = g_part[2*CB + tid];
    __syncthreads();
#pragma unroll
    for (int s = CB / 2; s > 0; s >>= 1) {
        if (tid < s) {
            r[tid]        += r[tid + s];
            r[CB + tid]   += r[CB + tid + s];
            r[2*CB + tid] += r[2*CB + tid + s];
        }
        __syncthreads();
    }
    if (tid == 0) {
        const float invBN = 1.0f / (float)BN;
        float density_loss   = r[0] * invBN;
        float direction_loss = 1.0f - r[CB] * (invBN / (float)Kk);
        float curvature_loss = r[2*CB] * invBN;
        out[0] = density_loss + 0.5f * direction_loss + 0.5f * curvature_loss;
    }
}

extern "C" void kernel_launch(void* const* d_in, const int* in_sizes, int n_in,
                              void* d_out, int out_size) {
    (void)in_sizes; (void)n_in; (void)out_size;
    const float* pred   = (const float*)d_in[0];
    const float* target = (const float*)d_in[1];

    size_t smem_bytes = (size_t)Nn * sizeof(float4)
                      + (size_t)PPB * 9 * sizeof(unsigned);   // ~68.5 KB -> 2 CTAs/SM
    cudaFuncSetAttribute(knn_scan_kernel,
                         cudaFuncAttributeMaxDynamicSharedMemorySize,
                         (int)smem_bytes);

    dim3 grid(Nn / PPB, Bb, 2);                 // 256 blocks, 256 threads each
    knn_scan_kernel<<<grid, TPB, smem_bytes>>>(pred, target);
    combine_kernel<<<CB, CTPB>>>();
    finalize_kernel<<<1, CB>>>((float*)d_out);
}

// round 15
// speedup vs baseline: 1.0413x; 1.0413x over previous
#include <cuda_runtime.h>

#define Nn    4096
#define Bb    4
#define Kk    8
#define BN    (Bb * Nn)         // 16384 points per cloud
#define TPB   512               // 128 point-pairs x 4 candidate quarters
#define PPB   256               // points per block (two sets of 128)
#define QLEN  (Nn / 4)          // 1024 candidates per thread
#define CB    64
#define CTPB  256
#define EPSF  1e-12f
#define KINIT 0x7F7FF000u       // huge-float key; |0xFFF -> FLT_MAX threshold
#define BIGF  3.4e38f

// ---- device scratch (SoA, coalesced) ----
__device__ float g_dens[2 * BN];
__device__ float g_cov [2 * 6 * BN];
__device__ float g_nv  [2 * Kk * 3 * BN];
__device__ float g_part[3 * CB];

// Ladder-insert key v into ascending 9-list of u32 keys (branch-free, no-op
// safe when v exceeds kd[8]).
__device__ __forceinline__ void ladder9(unsigned kd[9], unsigned v) {
#pragma unroll
    for (int t = 0; t < 9; t++) {
        unsigned lo = umin(kd[t], v);
        v = umax(kd[t], v);
        kd[t] = lo;
    }
}

// Epilogue for one point: density, covariance, normalized neighbor vectors.
__device__ __forceinline__ void epilogue(const float4* __restrict__ sc,
                                         const unsigned kd[9], float4 Pi,
                                         int c, int base) {
    float dens = 0.f;
    float cxx = 0.f, cyy = 0.f, czz = 0.f, cxy = 0.f, cxz = 0.f, cyz = 0.f;
#pragma unroll
    for (int k = 0; k < Kk; k++) {
        int j = (int)(kd[k+1] & 0xFFFu);
        float4 q = sc[j];
        float vx = q.x - Pi.x, vy = q.y - Pi.y, vz = q.z - Pi.z;
        cxx = fmaf(vx, vx, cxx); cyy = fmaf(vy, vy, cyy); czz = fmaf(vz, vz, czz);
        cxy = fmaf(vx, vy, cxy); cxz = fmaf(vx, vz, cxz); cyz = fmaf(vy, vz, cyz);
        float nrm = sqrtf(fmaf(vx, vx, fmaf(vy, vy, vz * vz)));
        dens += fmaxf(nrm, 1e-6f);           // sqrt(max(d2,1e-12))
        float inv = 1.0f / fmaxf(nrm, EPSF);
        g_nv[((c*Kk + k)*3 + 0)*BN + base] = vx * inv;
        g_nv[((c*Kk + k)*3 + 1)*BN + base] = vy * inv;
        g_nv[((c*Kk + k)*3 + 2)*BN + base] = vz * inv;
    }
    g_dens[c*BN + base]        = dens * 0.125f;
    g_cov[(c*6 + 0)*BN + base] = cxx * 0.125f;
    g_cov[(c*6 + 1)*BN + base] = cyy * 0.125f;
    g_cov[(c*6 + 2)*BN + base] = czz * 0.125f;
    g_cov[(c*6 + 3)*BN + base] = cxy * 0.125f;
    g_cov[(c*6 + 4)*BN + base] = cxz * 0.125f;
    g_cov[(c*6 + 5)*BN + base] = cyz * 0.125f;
}

// Block: 256 points of one (batch, cloud). Thread t: points (t&127) and
// (t&127)+128, candidate quarter t>>7. One LDS.128 feeds both queries.
__global__ void __launch_bounds__(TPB)
knn_scan_kernel(const float* __restrict__ pred, const float* __restrict__ target) {
    extern __shared__ char smem_raw[];
    float4*   sc   = (float4*)smem_raw;                           // [Nn] cloud
    unsigned* lstk = (unsigned*)(smem_raw + Nn * sizeof(float4)); // [3][2][128][9]

    const int tid = threadIdx.x;
    const int b   = blockIdx.y;
    const int c   = blockIdx.z;              // 0 = pred, 1 = target
    const int pl  = tid & 127;               // local point (first of pair)
    const int qq  = tid >> 7;                // candidate quarter 0..3

    const float* src = (c == 0 ? pred : target) + (size_t)b * Nn * 3;
    for (int p = tid; p < Nn; p += TPB) {
        float x = src[3*p+0], y = src[3*p+1], z = src[3*p+2];
        sc[p] = make_float4(x, y, z, fmaf(x, x, fmaf(y, y, z*z)));
    }
    __syncthreads();

    const int iA = blockIdx.x * PPB + pl;
    const int iB = iA + 128;
    const float4 PA = sc[iA];
    const float4 PB = sc[iB];

    const float m2xA = -2.0f*PA.x, m2yA = -2.0f*PA.y, m2zA = -2.0f*PA.z;
    const float m2xB = -2.0f*PB.x, m2yB = -2.0f*PB.y, m2zB = -2.0f*PB.z;

    unsigned kdA[9], kdB[9];
#pragma unroll
    for (int t = 0; t < 9; t++) { kdA[t] = KINIT; kdB[t] = KINIT; }
    float thrA = BIGF, thrB = BIGF;          // thresholds in d2' space

    const int j0 = qq * QLEN, jend = j0 + QLEN;
#pragma unroll 4
    for (int j = j0; j < jend; j++) {
        float4 q = sc[j];
        float dA = fmaf(m2xA, q.x, fmaf(m2yA, q.y, fmaf(m2zA, q.z, q.w)));
        float dB = fmaf(m2xB, q.x, fmaf(m2yB, q.y, fmaf(m2zB, q.z, q.w)));
        if (__any_sync(0xffffffffu, dA <= thrA)) {
            float vc = fmaxf(dA + PA.w, 0.0f);
            ladder9(kdA, (__float_as_uint(vc) & 0xFFFFF000u) | (unsigned)j);
            thrA = __uint_as_float(kdA[8] | 0xFFFu) - PA.w;
        }
        if (__any_sync(0xffffffffu, dB <= thrB)) {
            float vc = fmaxf(dB + PB.w, 0.0f);
            ladder9(kdB, (__float_as_uint(vc) & 0xFFFFF000u) | (unsigned)j);
            thrB = __uint_as_float(kdB[8] | 0xFFFu) - PB.w;
        }
    }

    // quarters 1..3 publish both lists (stride-9)
    if (qq != 0) {
        unsigned* dA = lstk + (((qq - 1) * 2 + 0) * 128 + pl) * 9;
        unsigned* dB = lstk + (((qq - 1) * 2 + 1) * 128 + pl) * 9;
#pragma unroll
        for (int t = 0; t < 9; t++) { dA[t] = kdA[t]; dB[t] = kdB[t]; }
    }
    __syncthreads();
    if (qq != 0) return;

    // quarter 0 merges the 3 published lists per point (keys unique -> exact)
#pragma unroll
    for (int m = 0; m < 3; m++) {
        const unsigned* dA = lstk + ((m * 2 + 0) * 128 + pl) * 9;
        const unsigned* dB = lstk + ((m * 2 + 1) * 128 + pl) * 9;
#pragma unroll
        for (int t = 0; t < 9; t++) { ladder9(kdA, dA[t]); ladder9(kdB, dB[t]); }
    }

    epilogue(sc, kdA, PA, c, b * Nn + iA);
    epilogue(sc, kdB, PB, c, b * Nn + iB);
}

// Pair pred/target stats per point, partial-reduce per block.
__global__ void __launch_bounds__(CTPB)
combine_kernel() {
    const int tid = threadIdx.x;
    const int idx = blockIdx.x * CTPB + tid;

    float dd = g_dens[idx] - g_dens[BN + idx];
    float c_den = dd * dd;

    float fro = 0.f;
#pragma unroll
    for (int s = 0; s < 6; s++) {
        float e = g_cov[s*BN + idx] - g_cov[(6 + s)*BN + idx];
        float w = (s < 3) ? 1.0f : 2.0f;
        fro = fmaf(w * e, e, fro);
    }
    float c_cur = sqrtf(fro);

    float dsum = 0.f;
#pragma unroll
    for (int e = 0; e < Kk * 3; e++)
        dsum = fmaf(g_nv[e*BN + idx], g_nv[(Kk*3 + e)*BN + idx], dsum);

    __shared__ float r[3 * CTPB];
    r[tid]          = c_den;
    r[CTPB + tid]   = dsum;
    r[2*CTPB + tid] = c_cur;
    __syncthreads();
#pragma unroll
    for (int s = CTPB / 2; s > 0; s >>= 1) {
        if (tid < s) {
            r[tid]          += r[tid + s];
            r[CTPB + tid]   += r[CTPB + tid + s];
            r[2*CTPB + tid] += r[2*CTPB + tid + s];
        }
        __syncthreads();
    }
    if (tid == 0) {
        g_part[blockIdx.x]        = r[0];
        g_part[CB + blockIdx.x]   = r[CTPB];
        g_part[2*CB + blockIdx.x] = r[2*CTPB];
    }
}

__global__ void __launch_bounds__(CB) finalize_kernel(float* __restrict__ out) {
    __shared__ float r[3 * CB];
    int tid = threadIdx.x;
    r[tid]        = g_part[tid];
    r[CB + tid]   = g_part[CB + tid];
    r[2*CB + tid] = g_part[2*CB + tid];
    __syncthreads();
#pragma unroll
    for (int s = CB / 2; s > 0; s >>= 1) {
        if (tid < s) {
            r[tid]        += r[tid + s];
            r[CB + tid]   += r[CB + tid + s];
            r[2*CB + tid] += r[2*CB + tid + s];
        }
        __syncthreads();
    }
    if (tid == 0) {
        const float invBN = 1.0f / (float)BN;
        float density_loss   = r[0] * invBN;
        float direction_loss = 1.0f - r[CB] * (invBN / (float)Kk);
        float curvature_loss = r[2*CB] * invBN;
        out[0] = density_loss + 0.5f * direction_loss + 0.5f * curvature_loss;
    }
}

extern "C" void kernel_launch(void* const* d_in, const int* in_sizes, int n_in,
                              void* d_out, int out_size) {
    (void)in_sizes; (void)n_in; (void)out_size;
    const float* pred   = (const float*)d_in[0];
    const float* target = (const float*)d_in[1];

    size_t smem_bytes = (size_t)Nn * sizeof(float4)
                      + (size_t)3 * 2 * 128 * 9 * sizeof(unsigned); // ~91 KB
    cudaFuncSetAttribute(knn_scan_kernel,
                         cudaFuncAttributeMaxDynamicSharedMemorySize,
                         (int)smem_bytes);

    dim3 grid(Nn / PPB, Bb, 2);                 // 128 blocks, 512 threads each
    knn_scan_kernel<<<grid, TPB, smem_bytes>>>(pred, target);
    combine_kernel<<<CB, CTPB>>>();
    finalize_kernel<<<1, CB>>>((float*)d_out);
}

// round 16
// speedup vs baseline: 1.2431x; 1.1937x over previous
#include <cuda_runtime.h>

#define Nn    4096
#define Bb    4
#define Kk    8
#define BN    (Bb * Nn)         // 16384 points per cloud
#define TPB   512               // 256 points/block, 2 threads per point
#define PPB   256
#define HALF  (Nn / 2)          // candidates per thread
#define NW    (TPB / 32)        // 16 warps
#define SLOTS 12                // per-lane buffer capacity
#define WM    8                 // drain watermark (cap >= WM + 4 - 1)
#define CB    64
#define CTPB  256
#define EPSF  1e-12f
#define KINIT 0x7F7FF000u
#define BIGF  3.4e38f

// ---- device scratch (SoA, coalesced) ----
__device__ float g_dens[2 * BN];
__device__ float g_cov [2 * 6 * BN];
__device__ float g_nv  [2 * Kk * 3 * BN];
__device__ float g_part[3 * CB];

// Ladder-insert key v into ascending 9-list (branch-free; no-op if v too big).
__device__ __forceinline__ void ladder9(unsigned kd[9], unsigned v) {
#pragma unroll
    for (int t = 0; t < 9; t++) {
        unsigned lo = umin(kd[t], v);
        v = umax(kd[t], v);
        kd[t] = lo;
    }
}

// Drain <= SLOTS buffered candidate indices: recompute exact d2, pack key, insert.
__device__ __forceinline__ void drain9(unsigned kd[9],
                                       const unsigned* __restrict__ myb,
                                       int cnt, const float4* __restrict__ sc,
                                       float m2x, float m2y, float m2z, float sq) {
#pragma unroll
    for (int t = 0; t < SLOTS; t++) {
        unsigned jr = myb[t * 32] & (Nn - 1);          // clamp garbage in-bounds
        float4 q = sc[jr];
        float d2p = fmaf(m2x, q.x, fmaf(m2y, q.y, fmaf(m2z, q.z, q.w)));
        float d2  = fmaxf(d2p + sq, 0.0f);
        unsigned key = (__float_as_uint(d2) & 0xFFFFF000u) | jr;
        key = (t < cnt) ? key : 0xFFFFFFFFu;
        ladder9(kd, key);
    }
}

// Block: 256 points of one (batch, cloud), 2 threads/point (candidate halves).
__global__ void __launch_bounds__(TPB)
knn_scan_kernel(const float* __restrict__ pred, const float* __restrict__ target) {
    extern __shared__ char smem_raw[];
    float4*   sc   = (float4*)smem_raw;                            // 64 KB
    unsigned* lstk = (unsigned*)(smem_raw + Nn * sizeof(float4));  // PPB*9 (9 KB)
    unsigned* sbuf = lstk + PPB * 9;                               // NW*SLOTS*32 (24 KB)

    const int tid  = threadIdx.x;
    const int b    = blockIdx.y;
    const int c    = blockIdx.z;             // 0 = pred, 1 = target
    const int pl   = tid & (PPB - 1);
    const int half = tid >> 8;               // candidate half 0/1
    const int wid  = tid >> 5;
    const int lane = tid & 31;

    const float* src = (c == 0 ? pred : target) + (size_t)b * Nn * 3;
    for (int p = tid; p < Nn; p += TPB) {
        float x = src[3*p+0], y = src[3*p+1], z = src[3*p+2];
        sc[p] = make_float4(x, y, z, fmaf(x, x, fmaf(y, y, z*z)));
    }
    __syncthreads();

    const int i  = blockIdx.x * PPB + pl;
    const float4 Pi = sc[i];
    const float sq = Pi.w;
    const float m2x = -2.0f * Pi.x, m2y = -2.0f * Pi.y, m2z = -2.0f * Pi.z;

    unsigned kd[9];
#pragma unroll
    for (int t = 0; t < 9; t++) kd[t] = KINIT;
    float thr = BIGF;                         // threshold in d2' space
    unsigned* myb = sbuf + wid * (SLOTS * 32) + lane;
    int cnt = 0;

    const int j0 = half * HALF;
    for (int j4 = j0; j4 < j0 + HALF; j4 += 4) {
#pragma unroll
        for (int u = 0; u < 4; u++) {
            int j = j4 + u;
            float4 q = sc[j];
            float d2p = fmaf(m2x, q.x, fmaf(m2y, q.y, fmaf(m2z, q.z, q.w)));
            bool hit = d2p < thr;
            if (hit) myb[cnt * 32] = (unsigned)j;   // predicated STS.32
            cnt += hit;
        }
        if (__any_sync(0xffffffffu, cnt >= WM)) {   // rare, warp-uniform
            drain9(kd, myb, cnt, sc, m2x, m2y, m2z, sq);
            cnt = 0;
            thr = __uint_as_float(kd[8] | 0xFFFu) - sq;
        }
    }
    if (__any_sync(0xffffffffu, cnt > 0))
        drain9(kd, myb, cnt, sc, m2x, m2y, m2z, sq);

    // half-B publishes its sorted key list (stride-9)
    if (half == 1) {
        unsigned* dd = lstk + pl * 9;
#pragma unroll
        for (int t = 0; t < 9; t++) dd[t] = kd[t];
    }
    __syncthreads();
    if (half == 1) return;

    // merge B's keys into A's list (keys unique -> exact total order)
    {
        const unsigned* dd = lstk + pl * 9;
#pragma unroll
        for (int m = 0; m < 9; m++) ladder9(kd, dd[m]);
    }

    // ---- epilogue: slot 0 = self, slots 1..8 = the 8 neighbors ----
    const int base = b * Nn + i;
    float dens = 0.f;
    float cxx = 0.f, cyy = 0.f, czz = 0.f, cxy = 0.f, cxz = 0.f, cyz = 0.f;
#pragma unroll
    for (int k = 0; k < Kk; k++) {
        int j = (int)(kd[k+1] & 0xFFFu);
        float4 q = sc[j];
        float vx = q.x - Pi.x, vy = q.y - Pi.y, vz = q.z - Pi.z;
        cxx = fmaf(vx, vx, cxx); cyy = fmaf(vy, vy, cyy); czz = fmaf(vz, vz, czz);
        cxy = fmaf(vx, vy, cxy); cxz = fmaf(vx, vz, cxz); cyz = fmaf(vy, vz, cyz);
        float nrm = sqrtf(fmaf(vx, vx, fmaf(vy, vy, vz * vz)));
        dens += fmaxf(nrm, 1e-6f);            // sqrt(max(d2,1e-12))
        float inv = 1.0f / fmaxf(nrm, EPSF);
        g_nv[((c*Kk + k)*3 + 0)*BN + base] = vx * inv;
        g_nv[((c*Kk + k)*3 + 1)*BN + base] = vy * inv;
        g_nv[((c*Kk + k)*3 + 2)*BN + base] = vz * inv;
    }
    g_dens[c*BN + base]        = dens * 0.125f;
    g_cov[(c*6 + 0)*BN + base] = cxx * 0.125f;
    g_cov[(c*6 + 1)*BN + base] = cyy * 0.125f;
    g_cov[(c*6 + 2)*BN + base] = czz * 0.125f;
    g_cov[(c*6 + 3)*BN + base] = cxy * 0.125f;
    g_cov[(c*6 + 4)*BN + base] = cxz * 0.125f;
    g_cov[(c*6 + 5)*BN + base] = cyz * 0.125f;
}

// Pair pred/target stats per point, partial-reduce per block.
__global__ void __launch_bounds__(CTPB)
combine_kernel() {
    const int tid = threadIdx.x;
    const int idx = blockIdx.x * CTPB + tid;

    float dd = g_dens[idx] - g_dens[BN + idx];
    float c_den = dd * dd;

    float fro = 0.f;
#pragma unroll
    for (int s = 0; s < 6; s++) {
        float e = g_cov[s*BN + idx] - g_cov[(6 + s)*BN + idx];
        float w = (s < 3) ? 1.0f : 2.0f;
        fro = fmaf(w * e, e, fro);
    }
    float c_cur = sqrtf(fro);

    float dsum = 0.f;
#pragma unroll
    for (int e = 0; e < Kk * 3; e++)
        dsum = fmaf(g_nv[e*BN + idx], g_nv[(Kk*3 + e)*BN + idx], dsum);

    __shared__ float r[3 * CTPB];
    r[tid]          = c_den;
    r[CTPB + tid]   = dsum;
    r[2*CTPB + tid] = c_cur;
    __syncthreads();
#pragma unroll
    for (int s = CTPB / 2; s > 0; s >>= 1) {
        if (tid < s) {
            r[tid]          += r[tid + s];
            r[CTPB + tid]   += r[CTPB + tid + s];
            r[2*CTPB + tid] += r[2*CTPB + tid + s];
        }
        __syncthreads();
    }
    if (tid == 0) {
        g_part[blockIdx.x]        = r[0];
        g_part[CB + blockIdx.x]   = r[CTPB];
        g_part[2*CB + blockIdx.x] = r[2*CTPB];
    }
}

__global__ void __launch_bounds__(CB) finalize_kernel(float* __restrict__ out) {
    __shared__ float r[3 * CB];
    int tid = threadIdx.x;
    r[tid]        = g_part[tid];
    r[CB + tid]   = g_part[CB + tid];
    r[2*CB + tid] = g_part[2*CB + tid];
    __syncthreads();
#pragma unroll
    for (int s = CB / 2; s > 0; s >>= 1) {
        if (tid < s) {
            r[tid]        += r[tid + s];
            r[CB + tid]   += r[CB + tid + s];
            r[2*CB + tid] += r[2*CB + tid + s];
        }
        __syncthreads();
    }
    if (tid == 0) {
        const float invBN = 1.0f / (float)BN;
        float density_loss   = r[0] * invBN;
        float direction_loss = 1.0f - r[CB] * (invBN / (float)Kk);
        float curvature_loss = r[2*CB] * invBN;
        out[0] = density_loss + 0.5f * direction_loss + 0.5f * curvature_loss;
    }
}

extern "C" void kernel_launch(void* const* d_in, const int* in_sizes, int n_in,
                              void* d_out, int out_size) {
    (void)in_sizes; (void)n_in; (void)out_size;
    const float* pred   = (const float*)d_in[0];
    const float* target = (const float*)d_in[1];

    size_t smem_bytes = (size_t)Nn * sizeof(float4)                 // 64 KB cloud
                      + (size_t)PPB * 9 * sizeof(unsigned)          // 9 KB lists
                      + (size_t)NW * SLOTS * 32 * sizeof(unsigned); // 24 KB buffers
    cudaFuncSetAttribute(knn_scan_kernel,
                         cudaFuncAttributeMaxDynamicSharedMemorySize,
                         (int)smem_bytes);

    dim3 grid(Nn / PPB, Bb, 2);                 // 128 blocks, 512 threads each
    knn_scan_kernel<<<grid, TPB, smem_bytes>>>(pred, target);
    combine_kernel<<<CB, CTPB>>>();
    finalize_kernel<<<1, CB>>>((float*)d_out);
}

// round 17
// speedup vs baseline: 1.4255x; 1.1468x over previous
#include <cuda_runtime.h>

#define Nn    4096
#define Bb    4
#define Kk    8
#define BN    (Bb * Nn)         // 16384 points per cloud
#define NQ    4                 // candidate split factor
#define PPB   256               // points per block
#define TPB   (PPB * NQ)        // 1024 threads
#define QLEN  (Nn / NQ)         // 1024 candidates per thread
#define NW    (TPB / 32)        // 32 warps
#define SLOTS 16                // per-lane buffer capacity
#define WM    8                 // drain watermark (checked every 8 iters)
#define CB    64
#define CTPB  256
#define EPSF  1e-12f
#define KINIT 0x7F7FF000u
#define BIGF  3.4e38f

// ---- device scratch (SoA, coalesced) ----
__device__ float g_dens[2 * BN];
__device__ float g_cov [2 * 6 * BN];
__device__ float g_nv  [2 * Kk * 3 * BN];
__device__ float g_part[3 * CB];

// Ladder-insert key v into ascending 9-list (branch-free; no-op if v too big).
__device__ __forceinline__ void ladder9(unsigned kd[9], unsigned v) {
#pragma unroll
    for (int t = 0; t < 9; t++) {
        unsigned lo = umin(kd[t], v);
        v = umax(kd[t], v);
        kd[t] = lo;
    }
}

// Drain <= SLOTS buffered candidate indices: recompute exact d2, pack key, insert.
__device__ __forceinline__ void drain9(unsigned kd[9],
                                       const unsigned* __restrict__ myb,
                                       int cnt, const float4* __restrict__ sc,
                                       float m2x, float m2y, float m2z, float sq) {
#pragma unroll
    for (int t = 0; t < SLOTS; t++) {
        unsigned jr = myb[t * 32] & (Nn - 1);          // clamp garbage in-bounds
        float4 q = sc[jr];
        float d2p = fmaf(m2x, q.x, fmaf(m2y, q.y, fmaf(m2z, q.z, q.w)));
        float d2  = fmaxf(d2p + sq, 0.0f);
        unsigned key = (__float_as_uint(d2) & 0xFFFFF000u) | jr;
        key = (t < cnt) ? key : 0xFFFFFFFFu;
        ladder9(kd, key);
    }
}

// Block: 256 points of one (batch, cloud), 4 threads/point (candidate quarters).
__global__ void __launch_bounds__(TPB)
knn_scan_kernel(const float* __restrict__ pred, const float* __restrict__ target) {
    extern __shared__ char smem_raw[];
    float4*   sc   = (float4*)smem_raw;                            // 64 KB
    unsigned* lstk = (unsigned*)(smem_raw + Nn * sizeof(float4));  // 3*PPB*9 (27 KB)
    unsigned* sbuf = lstk + 3 * PPB * 9;                           // NW*SLOTS*32 (64 KB)

    const int tid  = threadIdx.x;
    const int b    = blockIdx.y;
    const int c    = blockIdx.z;             // 0 = pred, 1 = target
    const int pl   = tid & (PPB - 1);
    const int qq   = tid >> 8;               // candidate quarter 0..3
    const int wid  = tid >> 5;
    const int lane = tid & 31;

    const float* src = (c == 0 ? pred : target) + (size_t)b * Nn * 3;
    for (int p = tid; p < Nn; p += TPB) {
        float x = src[3*p+0], y = src[3*p+1], z = src[3*p+2];
        sc[p] = make_float4(x, y, z, fmaf(x, x, fmaf(y, y, z*z)));
    }
    __syncthreads();

    const int i  = blockIdx.x * PPB + pl;
    const float4 Pi = sc[i];
    const float sq = Pi.w;
    const float m2x = -2.0f * Pi.x, m2y = -2.0f * Pi.y, m2z = -2.0f * Pi.z;

    unsigned kd[9];
#pragma unroll
    for (int t = 0; t < 9; t++) kd[t] = KINIT;
    float thr = BIGF;                         // threshold in d2' space
    unsigned* myb = sbuf + wid * (SLOTS * 32) + lane;
    int cnt = 0;

    const int j0 = qq * QLEN;
    for (int j8 = j0; j8 < j0 + QLEN; j8 += 8) {
#pragma unroll
        for (int u = 0; u < 8; u++) {
            int j = j8 + u;
            float4 q = sc[j];
            float d2p = fmaf(m2x, q.x, fmaf(m2y, q.y, fmaf(m2z, q.z, q.w)));
            bool hit = d2p < thr;
            if (hit) myb[cnt * 32] = (unsigned)j;   // predicated STS.32
            cnt += hit;
        }
        if (__any_sync(0xffffffffu, cnt >= WM)) {   // rare, warp-uniform
            drain9(kd, myb, cnt, sc, m2x, m2y, m2z, sq);
            cnt = 0;
            thr = __uint_as_float(kd[8] | 0xFFFu) - sq;
        }
    }
    if (__any_sync(0xffffffffu, cnt > 0))
        drain9(kd, myb, cnt, sc, m2x, m2y, m2z, sq);

    // quarters 1..3 publish their sorted key lists (stride-9)
    if (qq != 0) {
        unsigned* dd = lstk + ((qq - 1) * PPB + pl) * 9;
#pragma unroll
        for (int t = 0; t < 9; t++) dd[t] = kd[t];
    }
    __syncthreads();
    if (qq != 0) return;

    // quarter 0 merges Q1..Q3 keys (keys unique -> exact total order)
#pragma unroll
    for (int m = 0; m < 3; m++) {
        const unsigned* dd = lstk + (m * PPB + pl) * 9;
#pragma unroll
        for (int t = 0; t < 9; t++) ladder9(kd, dd[t]);
    }

    // ---- epilogue: slot 0 = self, slots 1..8 = the 8 neighbors ----
    const int base = b * Nn + i;
    float dens = 0.f;
    float cxx = 0.f, cyy = 0.f, czz = 0.f, cxy = 0.f, cxz = 0.f, cyz = 0.f;
#pragma unroll
    for (int k = 0; k < Kk; k++) {
        int j = (int)(kd[k+1] & 0xFFFu);
        float4 q = sc[j];
        float vx = q.x - Pi.x, vy = q.y - Pi.y, vz = q.z - Pi.z;
        cxx = fmaf(vx, vx, cxx); cyy = fmaf(vy, vy, cyy); czz = fmaf(vz, vz, czz);
        cxy = fmaf(vx, vy, cxy); cxz = fmaf(vx, vz, cxz); cyz = fmaf(vy, vz, cyz);
        float nrm = sqrtf(fmaf(vx, vx, fmaf(vy, vy, vz * vz)));
        dens += fmaxf(nrm, 1e-6f);            // sqrt(max(d2,1e-12))
        float inv = 1.0f / fmaxf(nrm, EPSF);
        g_nv[((c*Kk + k)*3 + 0)*BN + base] = vx * inv;
        g_nv[((c*Kk + k)*3 + 1)*BN + base] = vy * inv;
        g_nv[((c*Kk + k)*3 + 2)*BN + base] = vz * inv;
    }
    g_dens[c*BN + base]        = dens * 0.125f;
    g_cov[(c*6 + 0)*BN + base] = cxx * 0.125f;
    g_cov[(c*6 + 1)*BN + base] = cyy * 0.125f;
    g_cov[(c*6 + 2)*BN + base] = czz * 0.125f;
    g_cov[(c*6 + 3)*BN + base] = cxy * 0.125f;
    g_cov[(c*6 + 4)*BN + base] = cxz * 0.125f;
    g_cov[(c*6 + 5)*BN + base] = cyz * 0.125f;
}

// Pair pred/target stats per point, partial-reduce per block.
__global__ void __launch_bounds__(CTPB)
combine_kernel() {
    const int tid = threadIdx.x;
    const int idx = blockIdx.x * CTPB + tid;

    float dd = g_dens[idx] - g_dens[BN + idx];
    float c_den = dd * dd;

    float fro = 0.f;
#pragma unroll
    for (int s = 0; s < 6; s++) {
        float e = g_cov[s*BN + idx] - g_cov[(6 + s)*BN + idx];
        float w = (s < 3) ? 1.0f : 2.0f;
        fro = fmaf(w * e, e, fro);
    }
    float c_cur = sqrtf(fro);

    float dsum = 0.f;
#pragma unroll
    for (int e = 0; e < Kk * 3; e++)
        dsum = fmaf(g_nv[e*BN + idx], g_nv[(Kk*3 + e)*BN + idx], dsum);

    __shared__ float r[3 * CTPB];
    r[tid]          = c_den;
    r[CTPB + tid]   = dsum;
    r[2*CTPB + tid] = c_cur;
    __syncthreads();
#pragma unroll
    for (int s = CTPB / 2; s > 0; s >>= 1) {
        if (tid < s) {
            r[tid]          += r[tid + s];
            r[CTPB + tid]   += r[CTPB + tid + s];
            r[2*CTPB + tid] += r[2*CTPB + tid + s];
        }
        __syncthreads();
    }
    if (tid == 0) {
        g_part[blockIdx.x]        = r[0];
        g_part[CB + blockIdx.x]   = r[CTPB];
        g_part[2*CB + blockIdx.x] = r[2*CTPB];
    }
}

__global__ void __launch_bounds__(CB) finalize_kernel(float* __restrict__ out) {
    __shared__ float r[3 * CB];
    int tid = threadIdx.x;
    r[tid]        = g_part[tid];
    r[CB + tid]   = g_part[CB + tid];
    r[2*CB + tid] = g_part[2*CB + tid];
    __syncthreads();
#pragma unroll
    for (int s = CB / 2; s > 0; s >>= 1) {
        if (tid < s) {
            r[tid]        += r[tid + s];
            r[CB + tid]   += r[CB + tid + s];
            r[2*CB + tid] += r[2*CB + tid + s];
        }
        __syncthreads();
    }
    if (tid == 0) {
        const float invBN = 1.0f / (float)BN;
        float density_loss   = r[0] * invBN;
        float direction_loss = 1.0f - r[CB] * (invBN / (float)Kk);
        float curvature_loss = r[2*CB] * invBN;
        out[0] = density_loss + 0.5f * direction_loss + 0.5f * curvature_loss;
    }
}

extern "C" void kernel_launch(void* const* d_in, const int* in_sizes, int n_in,
                              void* d_out, int out_size) {
    (void)in_sizes; (void)n_in; (void)out_size;
    const float* pred   = (const float*)d_in[0];
    const float* target = (const float*)d_in[1];

    size_t smem_bytes = (size_t)Nn * sizeof(float4)                 // 64 KB cloud
                      + (size_t)3 * PPB * 9 * sizeof(unsigned)      // 27 KB lists
                      + (size_t)NW * SLOTS * 32 * sizeof(unsigned); // 64 KB buffers
    cudaFuncSetAttribute(knn_scan_kernel,
                         cudaFuncAttributeMaxDynamicSharedMemorySize,
                         (int)smem_bytes);

    dim3 grid(Nn / PPB, Bb, 2);                 // 128 blocks, 1024 threads each
    knn_scan_kernel<<<grid, TPB, smem_bytes>>>(pred, target);
    combine_kernel<<<CB, CTPB>>>();
    finalize_kernel<<<1, CB>>>((float*)d_out);
}